// round 4
// baseline (speedup 1.0000x reference)
#include <cuda_runtime.h>
#include <cstdint>

// Problem constants (fixed by the reference)
#define KFEAT   128      // NUM_FEATURES
#define NTHETA  32       // NUM_THETAS
#define NSTEP   32       // BUMP_STEPS
#define TILE_N  128      // nodes per block tile
#define KC      32       // k-chunk staged in shared
#define NTHREADS 256
#define XPAD    132      // xT row pitch (multiple of 4 for LDS.128)
#define HP      33       // acc/hist pitch to spread banks

__device__ __forceinline__ float fast_sigmoid(float z) {
    float e = __expf(-z);
    return __fdividef(1.0f, 1.0f + e);
}

__global__ void zero_kernel(float* __restrict__ out, int n) {
    int i = blockIdx.x * blockDim.x + threadIdx.x;
    if (i < n) out[i] = 0.0f;
}

union F4U { float4 v; float f[4]; };

__global__ void __launch_bounds__(NTHREADS, 3)
ect_fused_kernel(const float* __restrict__ x,
                 const void*  __restrict__ batch_raw,
                 const float* __restrict__ v,
                 float* __restrict__ out,
                 int n_nodes)
{
    __shared__ float xT[KC * XPAD];                 // transposed x chunk
    __shared__ float vs[NTHETA * KFEAT];            // full v, [t][k]
    __shared__ float accs[NSTEP * HP];              // transition sigmoid partials
    __shared__ int   hist[NSTEP * HP];              // mid-band step histogram (bins 1..31)
    __shared__ int   base_sh[NTHETA];               // "contributes to all s" counts
    __shared__ float cs_sh[NSTEP];                  // pad term c[s]
    __shared__ int   bsh[TILE_N];
    __shared__ int   s_segend;

    const int tid = threadIdx.x;
    const int ng  = tid & 31;     // lane: node group (4 nodes each)
    const int tg  = tid >> 5;     // warp: theta group (4 thetas each)
    const int tile_base = blockIdx.x * TILE_N;
    const int valid_n = min(TILE_N, n_nodes - tile_base);

    const float Rr       = 1.1f;
    const float STEP     = 2.2f / 31.0f;
    const float INV_STEP = 31.0f / 2.2f;
    const float SCALE    = 100.0f;
    const float Wb       = 0.05f * INV_STEP;   // z threshold 5 -> snap err e^-5 (abs ~0.03, negligible)

    // Detect batch dtype: int64 (JAX x64 on) vs int32 (default).
    const unsigned* bw = (const unsigned*)batch_raw;
    const bool is64 = (bw[n_nodes - 1] == 0u);

    // Stage v
    {
        const float4* v4 = (const float4*)v;
        float4* vs4 = (float4*)vs;
        #pragma unroll
        for (int j = 0; j < (NTHETA * KFEAT / 4) / NTHREADS; ++j)
            vs4[j * NTHREADS + tid] = v4[j * NTHREADS + tid];
    }
    // Stage batch labels + pad-sigmoid table
    if (tid < TILE_N) {
        int n = tile_base + tid;
        int b = 0x7fffffff;
        if (n < n_nodes)
            b = is64 ? (int)((const long long*)batch_raw)[n]
                     : ((const int*)batch_raw)[n];
        bsh[tid] = b;
    }
    if (tid >= TILE_N && tid < TILE_N + NSTEP) {
        int s = tid - TILE_N;
        float lin = fmaf((float)s, STEP, -Rr);
        float zc  = SCALE * (lin - Rr);
        cs_sh[s] = (zc > -25.0f) ? fast_sigmoid(zc) : 0.0f;
    }

    // ---- GEMM: nh tile in registers, 4 nodes x 4 thetas per thread ----
    float acc[4][4];
    #pragma unroll
    for (int i = 0; i < 4; ++i)
        #pragma unroll
        for (int j = 0; j < 4; ++j) acc[i][j] = 0.0f;

    // Register prefetch pipeline: 4 float4 per thread per chunk.
    float4 pre[4];
    #pragma unroll
    for (int it = 0; it < 4; ++it) {
        int idx = it * NTHREADS + tid;
        int r = idx >> 3, q = idx & 7;
        int n = tile_base + r;
        if (n >= n_nodes) n = n_nodes - 1;
        pre[it] = *(const float4*)(x + (size_t)n * KFEAT + q * 4);
    }

    #pragma unroll 1
    for (int kc = 0; kc < KFEAT / KC; ++kc) {
        __syncthreads();                 // smem safe to overwrite (also covers init staging)
        #pragma unroll
        for (int it = 0; it < 4; ++it) {
            int idx = it * NTHREADS + tid;
            int r = idx >> 3, q = idx & 7;
            xT[(q * 4 + 0) * XPAD + r] = pre[it].x;
            xT[(q * 4 + 1) * XPAD + r] = pre[it].y;
            xT[(q * 4 + 2) * XPAD + r] = pre[it].z;
            xT[(q * 4 + 3) * XPAD + r] = pre[it].w;
        }
        if (kc + 1 < KFEAT / KC) {       // issue next chunk's LDGs; latency hides under compute
            #pragma unroll
            for (int it = 0; it < 4; ++it) {
                int idx = it * NTHREADS + tid;
                int r = idx >> 3, q = idx & 7;
                int n = tile_base + r;
                if (n >= n_nodes) n = n_nodes - 1;
                pre[it] = *(const float4*)(x + (size_t)n * KFEAT + (kc + 1) * KC + q * 4);
            }
        }
        __syncthreads();
        #pragma unroll
        for (int kk4 = 0; kk4 < KC / 4; ++kk4) {
            F4U vv[4];
            #pragma unroll
            for (int j = 0; j < 4; ++j)   // warp-uniform (broadcast LDS, ~free)
                vv[j].v = *(const float4*)&vs[(4 * tg + j) * KFEAT + kc * KC + kk4 * 4];
            #pragma unroll
            for (int u = 0; u < 4; ++u) {
                float4 xx = *(const float4*)&xT[(kk4 * 4 + u) * XPAD + 4 * ng];
                #pragma unroll
                for (int j = 0; j < 4; ++j) {
                    float vb = vv[j].f[u];
                    acc[0][j] = fmaf(xx.x, vb, acc[0][j]);
                    acc[1][j] = fmaf(xx.y, vb, acc[1][j]);
                    acc[2][j] = fmaf(xx.z, vb, acc[2][j]);
                    acc[3][j] = fmaf(xx.w, vb, acc[3][j]);
                }
            }
        }
    }

    // ---- Epilogue: step decomposition, atomic-minimized ----
    int seg_start = 0;
    #pragma unroll 1
    while (seg_start < valid_n) {
        __syncthreads();                      // previous flush done before re-zeroing
        const int g = bsh[seg_start];
        if (tid == 0) s_segend = valid_n;
        for (int i2 = tid; i2 < NSTEP * HP; i2 += NTHREADS) { accs[i2] = 0.0f; hist[i2] = 0; }
        if (tid < NTHETA) base_sh[tid] = 0;
        __syncthreads();
        if (tid < valid_n && tid > seg_start && bsh[tid] != g)
            atomicMin(&s_segend, tid);        // sorted batch -> first mismatch = seg end
        __syncthreads();
        const int seg_end = s_segend;

        int basec0 = 0, basec1 = 0, basec2 = 0, basec3 = 0;

        #pragma unroll
        for (int i = 0; i < 4; ++i) {
            const int n_local = 4 * ng + i;
            const bool valid = (n_local >= seg_start) && (n_local < seg_end);
            #pragma unroll
            for (int j = 0; j < 4; ++j) {
                const int t = 4 * tg + j;
                float nh = acc[i][j];
                float a  = (nh + Rr) * INV_STEP;        // crossing position in s-units
                int ihi  = __float2int_ru(a + Wb);      // first s with full contribution
                ihi = max(0, min(NSTEP, ihi));

                // ihi==0 nodes (contribute 1 to every s): ballot-aggregate, no atomic.
                unsigned bal = __ballot_sync(0xffffffffu, valid && (ihi == 0));
                int bp = __popc(bal);
                if (j == 0) basec0 += bp;
                else if (j == 1) basec1 += bp;
                else if (j == 2) basec2 += bp;
                else basec3 += bp;

                // Mid-band hist: aggregate equal-bin lanes, single atomic per distinct bin.
                bool mid = valid && (ihi >= 1) && (ihi <= 31);
                unsigned key = mid ? (unsigned)ihi : (64u + (unsigned)ng);
                unsigned mmask = __match_any_sync(0xffffffffu, key);
                if (mid && ng == (__ffs(mmask) - 1))
                    atomicAdd(&hist[ihi * HP + t], __popc(mmask));

                if (valid) {
                    int s0 = max(0, __float2int_ru(a - Wb));
                    int s1 = min(ihi, NSTEP);
                    #pragma unroll 1
                    for (int s = s0; s < s1; ++s) {     // ~1-2 transition samples
                        float lin = fmaf((float)s, STEP, -Rr);
                        atomicAdd(&accs[s * HP + t], fast_sigmoid(SCALE * (lin - nh)));
                    }
                }
            }
        }
        // Flush warp-uniform base counts: lanes 0..3 each post one value.
        if (ng == 0) atomicAdd(&base_sh[4 * tg + 0], basec0);
        if (ng == 1) atomicAdd(&base_sh[4 * tg + 1], basec1);
        if (ng == 2) atomicAdd(&base_sh[4 * tg + 2], basec2);
        if (ng == 3) atomicAdd(&base_sh[4 * tg + 3], basec3);
        __syncthreads();

        if (tid < NTHETA) {                   // suffix-sum + flush: one thread per theta
            int t = tid;
            float run = (float)base_sh[t];
            float cnt = (float)(seg_end - seg_start);
            float* og = out + (size_t)g * (NSTEP * NTHETA);
            #pragma unroll 1
            for (int s = 0; s < NSTEP; ++s) {
                run += (float)hist[s * HP + t];
                float val = accs[s * HP + t] + run - cnt * cs_sh[s];
                atomicAdd(&og[s * NTHETA + t], val);
            }
        }
        seg_start = seg_end;
    }
}

extern "C" void kernel_launch(void* const* d_in, const int* in_sizes, int n_in,
                              void* d_out, int out_size) {
    // Identify inputs by element count: x = largest; v = 32*128; batch = n_nodes.
    int xi = 0; long long best = -1;
    for (int i = 0; i < n_in; ++i)
        if ((long long)in_sizes[i] > best) { best = in_sizes[i]; xi = i; }
    const float* x = (const float*)d_in[xi];
    int n_nodes = (int)(best / KFEAT);
    const void* batch = nullptr;
    const float* v = nullptr;
    for (int i = 0; i < n_in; ++i) {
        if (i == xi) continue;
        if (in_sizes[i] == NTHETA * KFEAT) v = (const float*)d_in[i];
        else if (in_sizes[i] == n_nodes)   batch = d_in[i];
    }
    float* out = (float*)d_out;

    zero_kernel<<<(out_size + 255) / 256, 256>>>(out, out_size);
    int tiles = (n_nodes + TILE_N - 1) / TILE_N;
    ect_fused_kernel<<<tiles, NTHREADS>>>(x, batch, v, out, n_nodes);
}

// round 5
// speedup vs baseline: 1.0190x; 1.0190x over previous
#include <cuda_runtime.h>
#include <cstdint>

// Problem constants (fixed by the reference)
#define KFEAT   128      // NUM_FEATURES
#define NTHETA  32       // NUM_THETAS
#define NSTEP   32       // BUMP_STEPS
#define TILE_N  256      // nodes per block tile
#define KC      16       // k-chunk staged in shared
#define NTHREADS 256
#define XPAD    260      // xT row pitch (multiple of 4 for LDS.128)
#define HP      33       // acc/hist pitch to spread banks

__device__ __forceinline__ float fast_sigmoid(float z) {
    float e = __expf(-z);
    return __fdividef(1.0f, 1.0f + e);
}

__global__ void zero_kernel(float* __restrict__ out, int n) {
    int i = blockIdx.x * blockDim.x + threadIdx.x;
    if (i < n) out[i] = 0.0f;
}

union F4U { float4 v; float f[4]; };

__global__ void __launch_bounds__(NTHREADS, 2)
ect_fused_kernel(const float* __restrict__ x,
                 const void*  __restrict__ batch_raw,
                 const float* __restrict__ v,
                 float* __restrict__ out,
                 int n_nodes)
{
    __shared__ float xT[KC * XPAD];                 // transposed x chunk (16.6 KB)
    __shared__ float vs[NTHETA * KFEAT];            // full v, [t][k]     (16 KB)
    __shared__ float accs[NSTEP * HP];              // transition sigmoid partials
    __shared__ int   hist[NSTEP * HP];              // mid-band step histogram (bins 1..31)
    __shared__ int   base_sh[NTHETA];               // "contributes to all s" counts
    __shared__ float cs_sh[NSTEP];                  // pad term c[s]
    __shared__ int   bsh[TILE_N];
    __shared__ int   s_segend;

    const int tid  = threadIdx.x;
    const int lane = tid & 31;
    const int slot = tid & 63;    // node slot (4 nodes each) -> 256 nodes
    const int tg   = tid >> 6;    // theta group (8 thetas each) -> 32 thetas
    const int tile_base = blockIdx.x * TILE_N;
    const int valid_n = min(TILE_N, n_nodes - tile_base);

    const float Rr       = 1.1f;
    const float STEP     = 2.2f / 31.0f;
    const float INV_STEP = 31.0f / 2.2f;
    const float SCALE    = 100.0f;
    const float Wb       = 0.05f * INV_STEP;   // z threshold 5

    // Detect batch dtype: int64 (JAX x64 on) vs int32 (default).
    const unsigned* bw = (const unsigned*)batch_raw;
    const bool is64 = (bw[n_nodes - 1] == 0u);

    // Stage v: 1024 float4, 4 per thread
    {
        const float4* v4 = (const float4*)v;
        float4* vs4 = (float4*)vs;
        #pragma unroll
        for (int j = 0; j < (NTHETA * KFEAT / 4) / NTHREADS; ++j)
            vs4[j * NTHREADS + tid] = v4[j * NTHREADS + tid];
    }
    // Stage batch labels + pad-sigmoid table
    {
        int n = tile_base + tid;
        int b = 0x7fffffff;
        if (n < n_nodes)
            b = is64 ? (int)((const long long*)batch_raw)[n]
                     : ((const int*)batch_raw)[n];
        bsh[tid] = b;
    }
    if (tid < NSTEP) {
        float lin = fmaf((float)tid, STEP, -Rr);
        float zc  = SCALE * (lin - Rr);
        cs_sh[tid] = (zc > -25.0f) ? fast_sigmoid(zc) : 0.0f;
    }

    // ---- GEMM: 4 nodes x 8 thetas per thread ----
    float acc[4][8];
    #pragma unroll
    for (int i = 0; i < 4; ++i)
        #pragma unroll
        for (int j = 0; j < 8; ++j) acc[i][j] = 0.0f;

    // Register prefetch: 4 float4 per thread per chunk (TILE_N*KC/4/NTHREADS = 4)
    float4 pre[4];
    #pragma unroll
    for (int it = 0; it < 4; ++it) {
        int idx = it * NTHREADS + tid;
        int r = idx >> 2, q = idx & 3;        // node row, float4-within-chunk
        int n = tile_base + r;
        if (n >= n_nodes) n = n_nodes - 1;
        pre[it] = *(const float4*)(x + (size_t)n * KFEAT + q * 4);
    }

    #pragma unroll 1
    for (int kc = 0; kc < KFEAT / KC; ++kc) {
        __syncthreads();
        #pragma unroll
        for (int it = 0; it < 4; ++it) {
            int idx = it * NTHREADS + tid;
            int r = idx >> 2, q = idx & 3;
            xT[(q * 4 + 0) * XPAD + r] = pre[it].x;
            xT[(q * 4 + 1) * XPAD + r] = pre[it].y;
            xT[(q * 4 + 2) * XPAD + r] = pre[it].z;
            xT[(q * 4 + 3) * XPAD + r] = pre[it].w;
        }
        if (kc + 1 < KFEAT / KC) {       // next chunk's LDGs hide under compute
            #pragma unroll
            for (int it = 0; it < 4; ++it) {
                int idx = it * NTHREADS + tid;
                int r = idx >> 2, q = idx & 3;
                int n = tile_base + r;
                if (n >= n_nodes) n = n_nodes - 1;
                pre[it] = *(const float4*)(x + (size_t)n * KFEAT + (kc + 1) * KC + q * 4);
            }
        }
        __syncthreads();
        #pragma unroll
        for (int kk4 = 0; kk4 < KC / 4; ++kk4) {
            F4U xx[4];
            #pragma unroll
            for (int u = 0; u < 4; ++u)      // 4 nodes x 4 k, conflict-free LDS.128
                xx[u].v = *(const float4*)&xT[(kk4 * 4 + u) * XPAD + 4 * slot];
            #pragma unroll
            for (int j = 0; j < 8; ++j) {
                F4U vvj;                     // warp-uniform broadcast LDS.128
                vvj.v = *(const float4*)&vs[(8 * tg + j) * KFEAT + kc * KC + kk4 * 4];
                #pragma unroll
                for (int u = 0; u < 4; ++u) {
                    float vb = vvj.f[u];
                    acc[0][j] = fmaf(xx[u].f[0], vb, acc[0][j]);
                    acc[1][j] = fmaf(xx[u].f[1], vb, acc[1][j]);
                    acc[2][j] = fmaf(xx[u].f[2], vb, acc[2][j]);
                    acc[3][j] = fmaf(xx[u].f[3], vb, acc[3][j]);
                }
            }
        }
    }

    // ---- Epilogue: step decomposition, atomic-minimized ----
    int seg_start = 0;
    #pragma unroll 1
    while (seg_start < valid_n) {
        __syncthreads();                      // previous flush done before re-zeroing
        const int g = bsh[seg_start];
        if (tid == 0) s_segend = valid_n;
        for (int i2 = tid; i2 < NSTEP * HP; i2 += NTHREADS) { accs[i2] = 0.0f; hist[i2] = 0; }
        if (tid < NTHETA) base_sh[tid] = 0;
        __syncthreads();
        if (tid < valid_n && tid > seg_start && bsh[tid] != g)
            atomicMin(&s_segend, tid);        // sorted batch -> first mismatch = seg end
        __syncthreads();
        const int seg_end = s_segend;

        int basec[8];
        #pragma unroll
        for (int j = 0; j < 8; ++j) basec[j] = 0;

        #pragma unroll
        for (int i = 0; i < 4; ++i) {
            const int n_local = 4 * slot + i;
            const bool valid = (n_local >= seg_start) && (n_local < seg_end);
            #pragma unroll
            for (int j = 0; j < 8; ++j) {
                const int t = 8 * tg + j;
                float nh = acc[i][j];
                float a  = (nh + Rr) * INV_STEP;        // crossing position in s-units
                int ihi  = __float2int_ru(a + Wb);      // first s with full contribution
                ihi = max(0, min(NSTEP, ihi));

                // ihi==0 nodes (contribute 1 to every s): ballot-aggregate, no atomic.
                unsigned bal = __ballot_sync(0xffffffffu, valid && (ihi == 0));
                basec[j] += __popc(bal);

                if (valid) {
                    if (ihi >= 1 && ihi <= 31)          // mid-band only (~30% of pairs)
                        atomicAdd(&hist[ihi * HP + t], 1);
                    int s0 = max(0, __float2int_ru(a - Wb));
                    int s1 = min(ihi, NSTEP);
                    #pragma unroll 1
                    for (int s = s0; s < s1; ++s) {     // ~1-2 transition samples
                        float lin = fmaf((float)s, STEP, -Rr);
                        atomicAdd(&accs[s * HP + t], fast_sigmoid(SCALE * (lin - nh)));
                    }
                }
            }
        }
        // Flush warp-uniform base counts: lane j posts basec[j] (unrolled, reg-resident).
        #pragma unroll
        for (int jj = 0; jj < 8; ++jj)
            if (lane == jj) atomicAdd(&base_sh[8 * tg + jj], basec[jj]);
        __syncthreads();

        if (tid < NTHETA) {                   // suffix-sum + flush: one thread per theta
            int t = tid;
            float run = (float)base_sh[t];
            float cnt = (float)(seg_end - seg_start);
            float* og = out + (size_t)g * (NSTEP * NTHETA);
            #pragma unroll 1
            for (int s = 0; s < NSTEP; ++s) {
                run += (float)hist[s * HP + t];
                float val = accs[s * HP + t] + run - cnt * cs_sh[s];
                atomicAdd(&og[s * NTHETA + t], val);
            }
        }
        seg_start = seg_end;
    }
}

extern "C" void kernel_launch(void* const* d_in, const int* in_sizes, int n_in,
                              void* d_out, int out_size) {
    // Identify inputs by element count: x = largest; v = 32*128; batch = n_nodes.
    int xi = 0; long long best = -1;
    for (int i = 0; i < n_in; ++i)
        if ((long long)in_sizes[i] > best) { best = in_sizes[i]; xi = i; }
    const float* x = (const float*)d_in[xi];
    int n_nodes = (int)(best / KFEAT);
    const void* batch = nullptr;
    const float* v = nullptr;
    for (int i = 0; i < n_in; ++i) {
        if (i == xi) continue;
        if (in_sizes[i] == NTHETA * KFEAT) v = (const float*)d_in[i];
        else if (in_sizes[i] == n_nodes)   batch = d_in[i];
    }
    float* out = (float*)d_out;

    zero_kernel<<<(out_size + 255) / 256, 256>>>(out, out_size);
    int tiles = (n_nodes + TILE_N - 1) / TILE_N;
    ect_fused_kernel<<<tiles, NTHREADS>>>(x, batch, v, out, n_nodes);
}

// round 10
// speedup vs baseline: 1.3290x; 1.3043x over previous
#include <cuda_runtime.h>
#include <cuda_bf16.h>
#include <cstdint>

// Problem constants (fixed by the reference)
#define KFEAT   128
#define NTHETA  32
#define NSTEP   32
#define TILE_N  256      // nodes per CTA (2 x 128-node rounds)
#define NTHREADS 256
#define HP      33       // acc/hist pitch

// ---- SMEM layout (bytes, dynamic) ----
// bf16 tiles at 256B row pitch, XOR swizzle on 16B seg index: s ^= (row & 7)
#define SA_HI     0          // 128 x 128 bf16 (32 KB)
#define SA_LO     32768
#define SB_HI     65536      // 32 x 128 bf16 (8 KB)
#define SB_LO     73728
#define SM_ACCS   81920      // 32*33 float
#define SM_HIST   86144      // 32*33 int
#define SM_BSH    90368      // 256 int
#define SM_BASE   91392      // 32 int
#define SM_CS     91520      // 32 float
#define SM_SEGEND 91648      // 4
#define SM_TOTAL  91656

__device__ __forceinline__ float fast_sigmoid(float z) {
    float e = __expf(-z);
    return __fdividef(1.0f, 1.0f + e);
}

union BU { __nv_bfloat162 h; unsigned u; };

__device__ __forceinline__ unsigned pack_hi(float a, float b, float& ra, float& rb) {
    BU u; u.h = __floats2bfloat162_rn(a, b);
    float2 f = __bfloat1622float2(u.h);
    ra = a - f.x; rb = b - f.y;
    return u.u;
}
__device__ __forceinline__ unsigned pack_lo(float a, float b) {
    BU u; u.h = __floats2bfloat162_rn(a, b); return u.u;
}

__device__ __forceinline__ void ldsm4(unsigned* r, uint32_t addr) {
    asm volatile("ldmatrix.sync.aligned.m8n8.x4.shared.b16 {%0,%1,%2,%3}, [%4];"
        : "=r"(r[0]), "=r"(r[1]), "=r"(r[2]), "=r"(r[3]) : "r"(addr));
}

static __device__ __forceinline__ uint32_t smem_u32(const void* p) {
    uint32_t a;
    asm("{ .reg .u64 t; cvta.to.shared.u64 t, %1; cvt.u32.u64 %0, t; }" : "=r"(a) : "l"(p));
    return a;
}

// D(m16n8) += A(m16k16,row) * B(k16n8,col) ; bf16 in, f32 acc
#define MMA(d0, d1, d2, d3, A, B0, B1) \
    asm volatile("mma.sync.aligned.m16n8k16.row.col.f32.bf16.bf16.f32 " \
        "{%0,%1,%2,%3}, {%4,%5,%6,%7}, {%8,%9}, {%0,%1,%2,%3};" \
        : "+f"(d0), "+f"(d1), "+f"(d2), "+f"(d3) \
        : "r"((A)[0]), "r"((A)[1]), "r"((A)[2]), "r"((A)[3]), "r"(B0), "r"(B1))

__global__ void zero_kernel(float* __restrict__ out, int n) {
    int i = blockIdx.x * blockDim.x + threadIdx.x;
    if (i < n) out[i] = 0.0f;
}

__global__ void __launch_bounds__(NTHREADS, 2)
ect_hmma_kernel(const float* __restrict__ x,
                const void*  __restrict__ batch_raw,
                const float* __restrict__ v,
                float* __restrict__ out,
                int n_nodes)
{
    extern __shared__ char smem[];
    const uint32_t sbase = smem_u32(smem);
    const int tid  = threadIdx.x;
    const int warp = tid >> 5;
    const int lane = tid & 31;
    const int g    = lane >> 2;     // fragment row group
    const int t4   = lane & 3;      // fragment col group
    const int tile_base = blockIdx.x * TILE_N;
    const int valid_n = min(TILE_N, n_nodes - tile_base);

    float* accs    = (float*)(smem + SM_ACCS);
    int*   hist    = (int*)  (smem + SM_HIST);
    int*   bsh     = (int*)  (smem + SM_BSH);
    int*   base_sh = (int*)  (smem + SM_BASE);
    float* cs_sh   = (float*)(smem + SM_CS);
    int*   segend  = (int*)  (smem + SM_SEGEND);

    const float Rr = 1.1f, STEP = 2.2f / 31.0f, INV_STEP = 31.0f / 2.2f;
    const float SCALE = 100.0f, Wb = 0.05f * INV_STEP;

    // batch dtype: int64 (JAX x64) vs int32 (default)
    const unsigned* bw = (const unsigned*)batch_raw;
    const bool is64 = (bw[n_nodes - 1] == 0u);

    // ---- Stage v -> B_hi/B_lo bf16 (32 rows x 256B) : 512 segs, 2/thread ----
    #pragma unroll
    for (int it = 0; it < 2; ++it) {
        int idx = it * NTHREADS + tid;
        int row = idx >> 4, s = idx & 15;
        const float4* p = (const float4*)(v + row * KFEAT + s * 8);
        float4 fa = p[0], fb = p[1];
        float r0, r1, r2, r3, r4, r5, r6, r7;
        uint4 H, L;
        H.x = pack_hi(fa.x, fa.y, r0, r1); H.y = pack_hi(fa.z, fa.w, r2, r3);
        H.z = pack_hi(fb.x, fb.y, r4, r5); H.w = pack_hi(fb.z, fb.w, r6, r7);
        L.x = pack_lo(r0, r1); L.y = pack_lo(r2, r3);
        L.z = pack_lo(r4, r5); L.w = pack_lo(r6, r7);
        int sw = row * 256 + (s ^ (row & 7)) * 16;
        *(uint4*)(smem + SB_HI + sw) = H;
        *(uint4*)(smem + SB_LO + sw) = L;
    }
    // batch labels + pad-sigmoid table
    {
        int n = tile_base + tid;
        int b = 0x7fffffff;
        if (n < n_nodes)
            b = is64 ? (int)((const long long*)batch_raw)[n] : ((const int*)batch_raw)[n];
        bsh[tid] = b;
    }
    if (tid < NSTEP) {
        float lin = fmaf((float)tid, STEP, -Rr);
        float zc  = SCALE * (lin - Rr);
        cs_sh[tid] = (zc > -25.0f) ? fast_sigmoid(zc) : 0.0f;
    }

    // ldmatrix per-lane row bases; swizzled seg index computed per k-chunk:
    //   addr = rowbase + (((kc*2 + h16) ^ (row&7)) << 4)
    const int l15 = lane & 15, h16 = lane >> 4;
    const int m7 = l15 & 7;
    const uint32_t rowA = sbase + (uint32_t)((warp * 16 + l15) * 256);
    const uint32_t rowB = sbase + (uint32_t)(l15 * 256);

    float acc[4][8];
    #pragma unroll
    for (int i = 0; i < 4; ++i)
        #pragma unroll
        for (int j = 0; j < 8; ++j) acc[i][j] = 0.0f;

    // ---- Two rounds: stage 128 nodes to bf16 hi/lo, HMMA accumulate ----
    #pragma unroll 1
    for (int rd = 0; rd < 2; ++rd) {
        __syncthreads();                  // v/batch staged (rd0) / prev round ldsm done (rd1)
        #pragma unroll
        for (int it = 0; it < 8; ++it) {  // 2048 segs, 8/thread
            int idx = it * NTHREADS + tid;
            int row = idx >> 4, s = idx & 15;
            int n = tile_base + rd * 128 + row;
            if (n >= n_nodes) n = n_nodes - 1;
            const float4* p = (const float4*)(x + (size_t)n * KFEAT + s * 8);
            float4 fa = p[0], fb = p[1];
            float r0, r1, r2, r3, r4, r5, r6, r7;
            uint4 H, L;
            H.x = pack_hi(fa.x, fa.y, r0, r1); H.y = pack_hi(fa.z, fa.w, r2, r3);
            H.z = pack_hi(fb.x, fb.y, r4, r5); H.w = pack_hi(fb.z, fb.w, r6, r7);
            L.x = pack_lo(r0, r1); L.y = pack_lo(r2, r3);
            L.z = pack_lo(r4, r5); L.w = pack_lo(r6, r7);
            int sw = row * 256 + (s ^ (row & 7)) * 16;
            *(uint4*)(smem + SA_HI + sw) = H;
            *(uint4*)(smem + SA_LO + sw) = L;
        }
        __syncthreads();

        const int i0 = rd * 2;
        #pragma unroll
        for (int kc = 0; kc < 8; ++kc) {
            const uint32_t so = (uint32_t)(((kc * 2 + h16) ^ m7) << 4);
            unsigned ah[4], al[4], bh[8], bl[8];
            ldsm4(ah, rowA + SA_HI + so);
            ldsm4(al, rowA + SA_LO + so);
            ldsm4(bh,     rowB + SB_HI + so);
            ldsm4(bh + 4, rowB + SB_HI + 4096 + so);
            ldsm4(bl,     rowB + SB_LO + so);
            ldsm4(bl + 4, rowB + SB_LO + 4096 + so);
            #pragma unroll
            for (int nt = 0; nt < 4; ++nt) {
                int bb = (nt >> 1) * 4 + (nt & 1);
                unsigned b0h = bh[bb], b1h = bh[bb + 2];
                unsigned b0l = bl[bb], b1l = bl[bb + 2];
                int j0 = nt * 2;
                MMA(acc[i0][j0], acc[i0][j0+1], acc[i0+1][j0], acc[i0+1][j0+1], ah, b0h, b1h);
                MMA(acc[i0][j0], acc[i0][j0+1], acc[i0+1][j0], acc[i0+1][j0+1], ah, b0l, b1l);
                MMA(acc[i0][j0], acc[i0][j0+1], acc[i0+1][j0], acc[i0+1][j0+1], al, b0h, b1h);
            }
        }
    }

    // Thread-owned nodes: acc[i][j] = nh[node_i][theta_j]
    //   node: i=0: w*16+g, i=1: +8, i=2: 128+w*16+g, i=3: 128+..+8
    //   theta: (j>>1)*8 + 2*t4 + (j&1)
    int nodes[4];
    nodes[0] = warp * 16 + g;       nodes[1] = nodes[0] + 8;
    nodes[2] = nodes[0] + 128;      nodes[3] = nodes[1] + 128;
    const unsigned tmask = 0x11111111u << t4;

    // ---- Epilogue: step decomposition per graph segment ----
    int seg_start = 0;
    #pragma unroll 1
    while (seg_start < valid_n) {
        __syncthreads();
        const int gg = bsh[seg_start];
        if (tid == 0) *segend = valid_n;
        for (int i2 = tid; i2 < NSTEP * HP; i2 += NTHREADS) { accs[i2] = 0.0f; hist[i2] = 0; }
        if (tid < NTHETA) base_sh[tid] = 0;
        __syncthreads();
        if (tid < valid_n && tid > seg_start && bsh[tid] != gg)
            atomicMin(segend, tid);
        __syncthreads();
        const int seg_end = *segend;

        int basec[8];
        #pragma unroll
        for (int j = 0; j < 8; ++j) basec[j] = 0;

        #pragma unroll
        for (int i = 0; i < 4; ++i) {
            const bool valid = (nodes[i] >= seg_start) && (nodes[i] < seg_end);
            #pragma unroll
            for (int j = 0; j < 8; ++j) {
                const int th = (j >> 1) * 8 + 2 * t4 + (j & 1);
                float nh = acc[i][j];
                float a  = (nh + Rr) * INV_STEP;
                int ihi  = __float2int_ru(a + Wb);
                ihi = max(0, min(NSTEP, ihi));
                unsigned bal = __ballot_sync(0xffffffffu, valid && (ihi == 0));
                basec[j] += __popc(bal & tmask);
                if (valid) {
                    if (ihi >= 1 && ihi <= 31)
                        atomicAdd(&hist[ihi * HP + th], 1);
                    int s0 = max(0, __float2int_ru(a - Wb));
                    int s1 = min(ihi, NSTEP);
                    #pragma unroll 1
                    for (int s = s0; s < s1; ++s) {
                        float lin = fmaf((float)s, STEP, -Rr);
                        atomicAdd(&accs[s * HP + th], fast_sigmoid(SCALE * (lin - nh)));
                    }
                }
            }
        }
        // lanes 0..3 are the t4==lane leaders for their theta set
        if (lane < 4) {
            #pragma unroll
            for (int j = 0; j < 8; ++j)
                atomicAdd(&base_sh[(j >> 1) * 8 + 2 * lane + (j & 1)], basec[j]);
        }
        __syncthreads();

        if (tid < NTHETA) {
            int th = tid;
            float run = (float)base_sh[th];
            float cnt = (float)(seg_end - seg_start);
            float* og = out + (size_t)gg * (NSTEP * NTHETA);
            #pragma unroll 1
            for (int s = 0; s < NSTEP; ++s) {
                run += (float)hist[s * HP + th];
                float val = accs[s * HP + th] + run - cnt * cs_sh[s];
                atomicAdd(&og[s * NTHETA + th], val);
            }
        }
        seg_start = seg_end;
    }
}

extern "C" void kernel_launch(void* const* d_in, const int* in_sizes, int n_in,
                              void* d_out, int out_size) {
    int xi = 0; long long best = -1;
    for (int i = 0; i < n_in; ++i)
        if ((long long)in_sizes[i] > best) { best = in_sizes[i]; xi = i; }
    const float* x = (const float*)d_in[xi];
    int n_nodes = (int)(best / KFEAT);
    const void* batch = nullptr;
    const float* v = nullptr;
    for (int i = 0; i < n_in; ++i) {
        if (i == xi) continue;
        if (in_sizes[i] == NTHETA * KFEAT) v = (const float*)d_in[i];
        else if (in_sizes[i] == n_nodes)   batch = d_in[i];
    }
    float* out = (float*)d_out;

    static bool attr_set = false;
    if (!attr_set) {
        cudaFuncSetAttribute(ect_hmma_kernel,
                             cudaFuncAttributeMaxDynamicSharedMemorySize, SM_TOTAL);
        attr_set = true;
    }
    zero_kernel<<<(out_size + 255) / 256, 256>>>(out, out_size);
    int tiles = (n_nodes + TILE_N - 1) / TILE_N;
    ect_hmma_kernel<<<tiles, NTHREADS, SM_TOTAL>>>(x, batch, v, out, n_nodes);
}

// round 11
// speedup vs baseline: 1.6007x; 1.2044x over previous
#include <cuda_runtime.h>
#include <cuda_bf16.h>
#include <cstdint>

// Problem constants (fixed by the reference)
#define KFEAT   128
#define NTHETA  32
#define NSTEP   32
#define TILE_N  256      // nodes per CTA (4 x 64-node rounds)
#define RN      64       // nodes per round
#define NROUND  4
#define NTHREADS 256
#define HP      33       // acc/hist pitch

// ---- SMEM layout (bytes, dynamic) ----
// bf16 tiles at 256B row pitch, XOR swizzle on 16B seg index: s ^= (row & 7)
#define SA_HI     0          // 64 x 128 bf16 (16 KB)
#define SA_LO     16384
#define SB_HI     32768      // 32 x 128 bf16 (8 KB)
#define SB_LO     40960
#define SM_ACCS   49152      // 32*33 float (4224)
#define SM_HIST   53376      // 32*33 int
#define SM_BSH    57600      // 256 int
#define SM_BASE   58624      // 32 int
#define SM_CS     58752      // 32 float
#define SM_SEGEND 58880      // 4
#define SM_TOTAL  58912

__device__ __forceinline__ float fast_sigmoid(float z) {
    float e = __expf(-z);
    return __fdividef(1.0f, 1.0f + e);
}

union BU { __nv_bfloat162 h; unsigned u; };

__device__ __forceinline__ unsigned pack_hi(float a, float b, float& ra, float& rb) {
    BU u; u.h = __floats2bfloat162_rn(a, b);
    float2 f = __bfloat1622float2(u.h);
    ra = a - f.x; rb = b - f.y;
    return u.u;
}
__device__ __forceinline__ unsigned pack_lo(float a, float b) {
    BU u; u.h = __floats2bfloat162_rn(a, b); return u.u;
}

__device__ __forceinline__ void ldsm4(unsigned* r, uint32_t addr) {
    asm volatile("ldmatrix.sync.aligned.m8n8.x4.shared.b16 {%0,%1,%2,%3}, [%4];"
        : "=r"(r[0]), "=r"(r[1]), "=r"(r[2]), "=r"(r[3]) : "r"(addr));
}

static __device__ __forceinline__ uint32_t smem_u32(const void* p) {
    uint32_t a;
    asm("{ .reg .u64 t; cvta.to.shared.u64 t, %1; cvt.u32.u64 %0, t; }" : "=r"(a) : "l"(p));
    return a;
}

// D(m16n8) += A(m16k16,row) * B(k16n8,col) ; bf16 in, f32 acc
#define MMA(d0, d1, d2, d3, A, B0, B1) \
    asm volatile("mma.sync.aligned.m16n8k16.row.col.f32.bf16.bf16.f32 " \
        "{%0,%1,%2,%3}, {%4,%5,%6,%7}, {%8,%9}, {%0,%1,%2,%3};" \
        : "+f"(d0), "+f"(d1), "+f"(d2), "+f"(d3) \
        : "r"((A)[0]), "r"((A)[1]), "r"((A)[2]), "r"((A)[3]), "r"(B0), "r"(B1))

__global__ void zero_kernel(float* __restrict__ out, int n) {
    int i = blockIdx.x * blockDim.x + threadIdx.x;
    if (i < n) out[i] = 0.0f;
}

__global__ void __launch_bounds__(NTHREADS, 3)
ect_hmma_kernel(const float* __restrict__ x,
                const void*  __restrict__ batch_raw,
                const float* __restrict__ v,
                float* __restrict__ out,
                int n_nodes)
{
    extern __shared__ char smem[];
    const uint32_t sbase = smem_u32(smem);
    const int tid  = threadIdx.x;
    const int warp = tid >> 5;
    const int lane = tid & 31;
    const int g    = lane >> 2;     // fragment row group
    const int t4   = lane & 3;      // fragment col group
    const int w4   = warp & 3;      // row-slice of the 64-node round
    const int half = warp >> 2;     // theta half: 0 -> th 0-15, 1 -> th 16-31
    const int tile_base = blockIdx.x * TILE_N;
    const int valid_n = min(TILE_N, n_nodes - tile_base);

    float* accs    = (float*)(smem + SM_ACCS);
    int*   hist    = (int*)  (smem + SM_HIST);
    int*   bsh     = (int*)  (smem + SM_BSH);
    int*   base_sh = (int*)  (smem + SM_BASE);
    float* cs_sh   = (float*)(smem + SM_CS);
    int*   segend  = (int*)  (smem + SM_SEGEND);

    const float Rr = 1.1f, STEP = 2.2f / 31.0f, INV_STEP = 31.0f / 2.2f;
    const float SCALE = 100.0f, Wb = 0.05f * INV_STEP;

    // batch dtype: int64 (JAX x64) vs int32 (default)
    const unsigned* bw = (const unsigned*)batch_raw;
    const bool is64 = (bw[n_nodes - 1] == 0u);

    // ---- Stage v -> B_hi/B_lo bf16 (32 rows x 256B): 512 segs, 2/thread ----
    #pragma unroll
    for (int it = 0; it < 2; ++it) {
        int idx = it * NTHREADS + tid;
        int row = idx >> 4, s = idx & 15;
        const float4* p = (const float4*)(v + row * KFEAT + s * 8);
        float4 fa = p[0], fb = p[1];
        float r0, r1, r2, r3, r4, r5, r6, r7;
        uint4 H, L;
        H.x = pack_hi(fa.x, fa.y, r0, r1); H.y = pack_hi(fa.z, fa.w, r2, r3);
        H.z = pack_hi(fb.x, fb.y, r4, r5); H.w = pack_hi(fb.z, fb.w, r6, r7);
        L.x = pack_lo(r0, r1); L.y = pack_lo(r2, r3);
        L.z = pack_lo(r4, r5); L.w = pack_lo(r6, r7);
        int sw = row * 256 + (s ^ (row & 7)) * 16;
        *(uint4*)(smem + SB_HI + sw) = H;
        *(uint4*)(smem + SB_LO + sw) = L;
    }
    // batch labels + pad-sigmoid table
    {
        int n = tile_base + tid;
        int b = 0x7fffffff;
        if (n < n_nodes)
            b = is64 ? (int)((const long long*)batch_raw)[n] : ((const int*)batch_raw)[n];
        bsh[tid] = b;
    }
    if (tid < NSTEP) {
        float lin = fmaf((float)tid, STEP, -Rr);
        float zc  = SCALE * (lin - Rr);
        cs_sh[tid] = (zc > -25.0f) ? fast_sigmoid(zc) : 0.0f;
    }

    // ldmatrix per-lane row bases; swizzled seg index per k-chunk:
    //   addr = rowbase + (((kc*2 + h16) ^ (row&7)) << 4)
    const int l15 = lane & 15, h16 = lane >> 4;
    const int m7 = l15 & 7;
    const uint32_t rowA = sbase + (uint32_t)((w4 * 16 + l15) * 256);
    const uint32_t rowB = sbase + (uint32_t)((half * 16 + l15) * 256);

    float acc[NROUND][8];
    #pragma unroll
    for (int i = 0; i < NROUND; ++i)
        #pragma unroll
        for (int j = 0; j < 8; ++j) acc[i][j] = 0.0f;

    // ---- Four rounds: stage 64 nodes to bf16 hi/lo, HMMA accumulate ----
    #pragma unroll 1
    for (int rd = 0; rd < NROUND; ++rd) {
        __syncthreads();                  // prev round ldsm done / init staging done
        #pragma unroll
        for (int it = 0; it < 4; ++it) {  // 1024 segs, 4/thread
            int idx = it * NTHREADS + tid;
            int row = idx >> 4, s = idx & 15;
            int n = tile_base + rd * RN + row;
            if (n >= n_nodes) n = n_nodes - 1;
            const float4* p = (const float4*)(x + (size_t)n * KFEAT + s * 8);
            float4 fa = p[0], fb = p[1];
            float r0, r1, r2, r3, r4, r5, r6, r7;
            uint4 H, L;
            H.x = pack_hi(fa.x, fa.y, r0, r1); H.y = pack_hi(fa.z, fa.w, r2, r3);
            H.z = pack_hi(fb.x, fb.y, r4, r5); H.w = pack_hi(fb.z, fb.w, r6, r7);
            L.x = pack_lo(r0, r1); L.y = pack_lo(r2, r3);
            L.z = pack_lo(r4, r5); L.w = pack_lo(r6, r7);
            int sw = row * 256 + (s ^ (row & 7)) * 16;
            *(uint4*)(smem + SA_HI + sw) = H;
            *(uint4*)(smem + SA_LO + sw) = L;
        }
        __syncthreads();

        #pragma unroll
        for (int kc = 0; kc < 8; ++kc) {
            const uint32_t so = (uint32_t)(((kc * 2 + h16) ^ m7) << 4);
            unsigned ah[4], al[4], bh[4], bl[4];
            ldsm4(ah, rowA + SA_HI + so);
            ldsm4(al, rowA + SA_LO + so);
            ldsm4(bh, rowB + SB_HI + so);
            ldsm4(bl, rowB + SB_LO + so);
            #pragma unroll
            for (int nb = 0; nb < 2; ++nb) {
                unsigned b0h = bh[nb], b1h = bh[nb + 2];
                unsigned b0l = bl[nb], b1l = bl[nb + 2];
                int j0 = nb * 4;
                MMA(acc[rd][j0], acc[rd][j0+1], acc[rd][j0+2], acc[rd][j0+3], ah, b0h, b1h);
                MMA(acc[rd][j0], acc[rd][j0+1], acc[rd][j0+2], acc[rd][j0+3], ah, b0l, b1l);
                MMA(acc[rd][j0], acc[rd][j0+1], acc[rd][j0+2], acc[rd][j0+3], al, b0h, b1h);
            }
        }
    }

    // Ownership: acc[rd][nb*4+c] = nh[node][theta]
    //   node  = rd*64 + w4*16 + g + (c>=2 ? 8 : 0)
    //   theta = half*16 + nb*8 + 2*t4 + (c&1)
    const int node_base = w4 * 16 + g;
    const unsigned tmask = 0x11111111u << t4;

    // ---- Epilogue: step decomposition per graph segment ----
    int seg_start = 0;
    #pragma unroll 1
    while (seg_start < valid_n) {
        __syncthreads();
        const int gg = bsh[seg_start];
        if (tid == 0) *segend = valid_n;
        for (int i2 = tid; i2 < NSTEP * HP; i2 += NTHREADS) { accs[i2] = 0.0f; hist[i2] = 0; }
        if (tid < NTHETA) base_sh[tid] = 0;
        __syncthreads();
        if (tid < valid_n && tid > seg_start && bsh[tid] != gg)
            atomicMin(segend, tid);
        __syncthreads();
        const int seg_end = *segend;

        int basec[8];
        #pragma unroll
        for (int j = 0; j < 8; ++j) basec[j] = 0;

        #pragma unroll
        for (int rd = 0; rd < NROUND; ++rd) {
            #pragma unroll
            for (int q = 0; q < 8; ++q) {
                const int nb = q >> 2, c = q & 3;
                const int node = rd * RN + node_base + ((c >= 2) ? 8 : 0);
                const int th = half * 16 + nb * 8 + 2 * t4 + (c & 1);
                const bool valid = (node >= seg_start) && (node < seg_end);
                float nh = acc[rd][q];
                float a  = (nh + Rr) * INV_STEP;
                int ihi  = __float2int_ru(a + Wb);
                ihi = max(0, min(NSTEP, ihi));
                unsigned bal = __ballot_sync(0xffffffffu, valid && (ihi == 0));
                basec[q] += __popc(bal & tmask);
                if (valid) {
                    if (ihi >= 1 && ihi <= 31)
                        atomicAdd(&hist[ihi * HP + th], 1);
                    int s0 = max(0, __float2int_ru(a - Wb));
                    int s1 = min(ihi, NSTEP);
                    #pragma unroll 1
                    for (int s = s0; s < s1; ++s) {
                        float lin = fmaf((float)s, STEP, -Rr);
                        atomicAdd(&accs[s * HP + th], fast_sigmoid(SCALE * (lin - nh)));
                    }
                }
            }
        }
        // lanes 0..3 are the t4==lane leaders; c and c+2 share theta -> sum.
        if (lane < 4) {
            #pragma unroll
            for (int nb = 0; nb < 2; ++nb)
                #pragma unroll
                for (int b01 = 0; b01 < 2; ++b01)
                    atomicAdd(&base_sh[half * 16 + nb * 8 + 2 * lane + b01],
                              basec[nb * 4 + b01] + basec[nb * 4 + 2 + b01]);
        }
        __syncthreads();

        if (tid < NTHETA) {
            int th = tid;
            float run = (float)base_sh[th];
            float cnt = (float)(seg_end - seg_start);
            float* og = out + (size_t)gg * (NSTEP * NTHETA);
            #pragma unroll 1
            for (int s = 0; s < NSTEP; ++s) {
                run += (float)hist[s * HP + th];
                float val = accs[s * HP + th] + run - cnt * cs_sh[s];
                atomicAdd(&og[s * NTHETA + th], val);
            }
        }
        seg_start = seg_end;
    }
}

extern "C" void kernel_launch(void* const* d_in, const int* in_sizes, int n_in,
                              void* d_out, int out_size) {
    int xi = 0; long long best = -1;
    for (int i = 0; i < n_in; ++i)
        if ((long long)in_sizes[i] > best) { best = in_sizes[i]; xi = i; }
    const float* x = (const float*)d_in[xi];
    int n_nodes = (int)(best / KFEAT);
    const void* batch = nullptr;
    const float* v = nullptr;
    for (int i = 0; i < n_in; ++i) {
        if (i == xi) continue;
        if (in_sizes[i] == NTHETA * KFEAT) v = (const float*)d_in[i];
        else if (in_sizes[i] == n_nodes)   batch = d_in[i];
    }
    float* out = (float*)d_out;

    static bool attr_set = false;
    if (!attr_set) {
        cudaFuncSetAttribute(ect_hmma_kernel,
                             cudaFuncAttributeMaxDynamicSharedMemorySize, SM_TOTAL);
        attr_set = true;
    }
    zero_kernel<<<(out_size + 255) / 256, 256>>>(out, out_size);
    int tiles = (n_nodes + TILE_N - 1) / TILE_N;
    ect_hmma_kernel<<<tiles, NTHREADS, SM_TOTAL>>>(x, batch, v, out, n_nodes);
}

// round 12
// speedup vs baseline: 1.8494x; 1.1554x over previous
#include <cuda_runtime.h>
#include <cuda_bf16.h>
#include <cstdint>

// Problem constants (fixed by the reference)
#define KFEAT   128
#define NTHETA  32
#define NSTEP   32
#define TILE_N  256      // nodes per CTA (4 x 64-node rounds)
#define RN      64       // nodes per round
#define NROUND  4
#define NTHREADS 256
#define HP      33       // diff-array pitch (bank spread)

// ---- SMEM layout (bytes, dynamic) ----
// bf16 tiles at 256B row pitch, XOR swizzle on 16B seg index: s ^= (row & 7)
#define SA_HI     0          // 64 x 128 bf16 (16 KB)
#define SA_LO     16384
#define SB_HI     32768      // 32 x 128 bf16 (8 KB)
#define SB_LO     40960
#define SM_ACCS   49152      // 32*33 float diff-array (4224)
#define SM_BSH    53376      // 256 int
#define SM_BASE   54400      // 32 int
#define SM_CS     54528      // 32 float
#define SM_SEGEND 54656      // 4
#define SM_TOTAL  54688

__device__ __forceinline__ float fast_sigmoid(float z) {
    float e = __expf(-z);
    return __fdividef(1.0f, 1.0f + e);
}

union BU { __nv_bfloat162 h; unsigned u; };

__device__ __forceinline__ unsigned pack_hi(float a, float b, float& ra, float& rb) {
    BU u; u.h = __floats2bfloat162_rn(a, b);
    float2 f = __bfloat1622float2(u.h);
    ra = a - f.x; rb = b - f.y;
    return u.u;
}
__device__ __forceinline__ unsigned pack_lo(float a, float b) {
    BU u; u.h = __floats2bfloat162_rn(a, b); return u.u;
}

__device__ __forceinline__ void ldsm4(unsigned* r, uint32_t addr) {
    asm volatile("ldmatrix.sync.aligned.m8n8.x4.shared.b16 {%0,%1,%2,%3}, [%4];"
        : "=r"(r[0]), "=r"(r[1]), "=r"(r[2]), "=r"(r[3]) : "r"(addr));
}

static __device__ __forceinline__ uint32_t smem_u32(const void* p) {
    uint32_t a;
    asm("{ .reg .u64 t; cvta.to.shared.u64 t, %1; cvt.u32.u64 %0, t; }" : "=r"(a) : "l"(p));
    return a;
}

// D(m16n8) += A(m16k16,row) * B(k16n8,col) ; bf16 in, f32 acc
#define MMA(d0, d1, d2, d3, A, B0, B1) \
    asm volatile("mma.sync.aligned.m16n8k16.row.col.f32.bf16.bf16.f32 " \
        "{%0,%1,%2,%3}, {%4,%5,%6,%7}, {%8,%9}, {%0,%1,%2,%3};" \
        : "+f"(d0), "+f"(d1), "+f"(d2), "+f"(d3) \
        : "r"((A)[0]), "r"((A)[1]), "r"((A)[2]), "r"((A)[3]), "r"(B0), "r"(B1))

__global__ void zero_kernel(float* __restrict__ out, int n) {
    int i = blockIdx.x * blockDim.x + threadIdx.x;
    if (i < n) out[i] = 0.0f;
}

__global__ void __launch_bounds__(NTHREADS, 3)
ect_hmma_kernel(const float* __restrict__ x,
                const void*  __restrict__ batch_raw,
                const float* __restrict__ v,
                float* __restrict__ out,
                int n_nodes)
{
    extern __shared__ char smem[];
    const uint32_t sbase = smem_u32(smem);
    const int tid  = threadIdx.x;
    const int warp = tid >> 5;
    const int lane = tid & 31;
    const int g    = lane >> 2;     // fragment row group
    const int t4   = lane & 3;      // fragment col group
    const int w4   = warp & 3;      // row-slice of the 64-node round
    const int half = warp >> 2;     // theta half: 0 -> th 0-15, 1 -> th 16-31
    const int tile_base = blockIdx.x * TILE_N;
    const int valid_n = min(TILE_N, n_nodes - tile_base);

    float* accs    = (float*)(smem + SM_ACCS);
    int*   bsh     = (int*)  (smem + SM_BSH);
    int*   base_sh = (int*)  (smem + SM_BASE);
    float* cs_sh   = (float*)(smem + SM_CS);
    int*   segend  = (int*)  (smem + SM_SEGEND);

    const float Rr = 1.1f, STEP = 2.2f / 31.0f, INV_STEP = 31.0f / 2.2f;
    const float SCALE = 100.0f;
    const float ZSTEP = SCALE * STEP;   // z-spacing between samples = 7.0968

    // batch dtype: int64 (JAX x64) vs int32 (default)
    const unsigned* bw = (const unsigned*)batch_raw;
    const bool is64 = (bw[n_nodes - 1] == 0u);

    // ---- Stage v -> B_hi/B_lo bf16 (32 rows x 256B): 512 segs, 2/thread ----
    #pragma unroll
    for (int it = 0; it < 2; ++it) {
        int idx = it * NTHREADS + tid;
        int row = idx >> 4, s = idx & 15;
        const float4* p = (const float4*)(v + row * KFEAT + s * 8);
        float4 fa = p[0], fb = p[1];
        float r0, r1, r2, r3, r4, r5, r6, r7;
        uint4 H, L;
        H.x = pack_hi(fa.x, fa.y, r0, r1); H.y = pack_hi(fa.z, fa.w, r2, r3);
        H.z = pack_hi(fb.x, fb.y, r4, r5); H.w = pack_hi(fb.z, fb.w, r6, r7);
        L.x = pack_lo(r0, r1); L.y = pack_lo(r2, r3);
        L.z = pack_lo(r4, r5); L.w = pack_lo(r6, r7);
        int sw = row * 256 + (s ^ (row & 7)) * 16;
        *(uint4*)(smem + SB_HI + sw) = H;
        *(uint4*)(smem + SB_LO + sw) = L;
    }
    // batch labels + pad-sigmoid table
    {
        int n = tile_base + tid;
        int b = 0x7fffffff;
        if (n < n_nodes)
            b = is64 ? (int)((const long long*)batch_raw)[n] : ((const int*)batch_raw)[n];
        bsh[tid] = b;
    }
    if (tid < NSTEP) {
        float lin = fmaf((float)tid, STEP, -Rr);
        float zc  = SCALE * (lin - Rr);
        cs_sh[tid] = (zc > -25.0f) ? fast_sigmoid(zc) : 0.0f;
    }

    // ldmatrix per-lane row bases; swizzled seg index per k-chunk:
    //   addr = rowbase + (((kc*2 + h16) ^ (row&7)) << 4)
    const int l15 = lane & 15, h16 = lane >> 4;
    const int m7 = l15 & 7;
    const uint32_t rowA = sbase + (uint32_t)((w4 * 16 + l15) * 256);
    const uint32_t rowB = sbase + (uint32_t)((half * 16 + l15) * 256);

    float acc[NROUND][8];
    #pragma unroll
    for (int i = 0; i < NROUND; ++i)
        #pragma unroll
        for (int j = 0; j < 8; ++j) acc[i][j] = 0.0f;

    // ---- Four rounds: stage 64 nodes to bf16 hi/lo, HMMA accumulate ----
    #pragma unroll 1
    for (int rd = 0; rd < NROUND; ++rd) {
        __syncthreads();                  // prev round ldsm done / init staging done
        #pragma unroll
        for (int it = 0; it < 4; ++it) {  // 1024 segs, 4/thread
            int idx = it * NTHREADS + tid;
            int row = idx >> 4, s = idx & 15;
            int n = tile_base + rd * RN + row;
            if (n >= n_nodes) n = n_nodes - 1;
            const float4* p = (const float4*)(x + (size_t)n * KFEAT + s * 8);
            float4 fa = p[0], fb = p[1];
            float r0, r1, r2, r3, r4, r5, r6, r7;
            uint4 H, L;
            H.x = pack_hi(fa.x, fa.y, r0, r1); H.y = pack_hi(fa.z, fa.w, r2, r3);
            H.z = pack_hi(fb.x, fb.y, r4, r5); H.w = pack_hi(fb.z, fb.w, r6, r7);
            L.x = pack_lo(r0, r1); L.y = pack_lo(r2, r3);
            L.z = pack_lo(r4, r5); L.w = pack_lo(r6, r7);
            int sw = row * 256 + (s ^ (row & 7)) * 16;
            *(uint4*)(smem + SA_HI + sw) = H;
            *(uint4*)(smem + SA_LO + sw) = L;
        }
        __syncthreads();

        #pragma unroll
        for (int kc = 0; kc < 8; ++kc) {
            const uint32_t so = (uint32_t)(((kc * 2 + h16) ^ m7) << 4);
            unsigned ah[4], al[4], bh[4], bl[4];
            ldsm4(ah, rowA + SA_HI + so);
            ldsm4(al, rowA + SA_LO + so);
            ldsm4(bh, rowB + SB_HI + so);
            ldsm4(bl, rowB + SB_LO + so);
            #pragma unroll
            for (int nb = 0; nb < 2; ++nb) {
                unsigned b0h = bh[nb], b1h = bh[nb + 2];
                unsigned b0l = bl[nb], b1l = bl[nb + 2];
                int j0 = nb * 4;
                MMA(acc[rd][j0], acc[rd][j0+1], acc[rd][j0+2], acc[rd][j0+3], ah, b0h, b1h);
                MMA(acc[rd][j0], acc[rd][j0+1], acc[rd][j0+2], acc[rd][j0+3], ah, b0l, b1l);
                MMA(acc[rd][j0], acc[rd][j0+1], acc[rd][j0+2], acc[rd][j0+3], al, b0h, b1h);
            }
        }
    }

    // Ownership: acc[rd][nb*4+c] = nh[node][theta]
    //   node  = rd*64 + w4*16 + g + (c>=2 ? 8 : 0)
    //   theta = half*16 + nb*8 + 2*t4 + (c&1)
    const int node_base = w4 * 16 + g;
    const unsigned tmask = 0x11111111u << t4;

    // ---- Epilogue: single-sample difference-array decomposition ----
    // z spacing between samples = 7.1 > 2*3.55 -> exactly one sample in the
    // sigmoid transition window: s* = round(a). Contributions per (node,th):
    //   s* <  0 : +1 at d[0]                      (ballot-aggregated)
    //   0<=s*<=31: +sig(z*) at d[s*], +(1-sig) at d[s*+1] (dropped if s*=31)
    //   s* > 31 : nothing
    // out[s] = prefix_sum(d)[s] - cnt*cs[s]
    int seg_start = 0;
    #pragma unroll 1
    while (seg_start < valid_n) {
        __syncthreads();
        const int gg = bsh[seg_start];
        if (tid == 0) *segend = valid_n;
        for (int i2 = tid; i2 < NSTEP * HP; i2 += NTHREADS) accs[i2] = 0.0f;
        if (tid < NTHETA) base_sh[tid] = 0;
        __syncthreads();
        if (tid < valid_n && tid > seg_start && bsh[tid] != gg)
            atomicMin(segend, tid);
        __syncthreads();
        const int seg_end = *segend;

        int basec[8];
        #pragma unroll
        for (int j = 0; j < 8; ++j) basec[j] = 0;

        #pragma unroll
        for (int rd = 0; rd < NROUND; ++rd) {
            #pragma unroll
            for (int q = 0; q < 8; ++q) {
                const int nb = q >> 2, c = q & 3;
                const int node = rd * RN + node_base + ((c >= 2) ? 8 : 0);
                const int th = half * 16 + nb * 8 + 2 * t4 + (c & 1);
                const bool valid = (node >= seg_start) && (node < seg_end);
                float nh = acc[rd][q];
                float a  = (nh + Rr) * INV_STEP;      // crossing position in s-units
                int ss   = __float2int_rn(a);         // the single transition sample
                unsigned bal = __ballot_sync(0xffffffffu, valid && (ss < 0));
                basec[q] += __popc(bal & tmask);
                if (valid && ss >= 0 && ss <= 31) {
                    float sg = fast_sigmoid(ZSTEP * ((float)ss - a));
                    atomicAdd(&accs[ss * HP + th], sg);
                    if (ss < 31)
                        atomicAdd(&accs[(ss + 1) * HP + th], 1.0f - sg);
                }
            }
        }
        // lanes 0..3 are the t4==lane leaders; c and c+2 share theta -> sum.
        if (lane < 4) {
            #pragma unroll
            for (int nb = 0; nb < 2; ++nb)
                #pragma unroll
                for (int b01 = 0; b01 < 2; ++b01)
                    atomicAdd(&base_sh[half * 16 + nb * 8 + 2 * lane + b01],
                              basec[nb * 4 + b01] + basec[nb * 4 + 2 + b01]);
        }
        __syncthreads();

        if (tid < NTHETA) {
            int th = tid;
            float run = (float)base_sh[th];
            float cnt = (float)(seg_end - seg_start);
            float* og = out + (size_t)gg * (NSTEP * NTHETA);
            #pragma unroll 1
            for (int s = 0; s < NSTEP; ++s) {
                run += accs[s * HP + th];
                float val = run - cnt * cs_sh[s];
                atomicAdd(&og[s * NTHETA + th], val);
            }
        }
        seg_start = seg_end;
    }
}

extern "C" void kernel_launch(void* const* d_in, const int* in_sizes, int n_in,
                              void* d_out, int out_size) {
    int xi = 0; long long best = -1;
    for (int i = 0; i < n_in; ++i)
        if ((long long)in_sizes[i] > best) { best = in_sizes[i]; xi = i; }
    const float* x = (const float*)d_in[xi];
    int n_nodes = (int)(best / KFEAT);
    const void* batch = nullptr;
    const float* v = nullptr;
    for (int i = 0; i < n_in; ++i) {
        if (i == xi) continue;
        if (in_sizes[i] == NTHETA * KFEAT) v = (const float*)d_in[i];
        else if (in_sizes[i] == n_nodes)   batch = d_in[i];
    }
    float* out = (float*)d_out;

    static bool attr_set = false;
    if (!attr_set) {
        cudaFuncSetAttribute(ect_hmma_kernel,
                             cudaFuncAttributeMaxDynamicSharedMemorySize, SM_TOTAL);
        attr_set = true;
    }
    zero_kernel<<<(out_size + 255) / 256, 256>>>(out, out_size);
    int tiles = (n_nodes + TILE_N - 1) / TILE_N;
    ect_hmma_kernel<<<tiles, NTHREADS, SM_TOTAL>>>(x, batch, v, out, n_nodes);
}